// round 15
// baseline (speedup 1.0000x reference)
#include <cuda_runtime.h>
#include <cuda_fp16.h>
#include <math.h>

#define N_NODES 100000
#define N_EDGES 3200000
#define NBLK_N 391
#define NBLK_E4 3125
#define NBLK_S 1563   // ceil(100000/64)

typedef unsigned long long u64;

#define GM_F32 0
#define GM_F16 1
#define GM_I8  2
#define GH_NONE 0
#define GH_F16  1
#define GH_I8   2

// ---------------- static device scratch (allocation-free) ----------------
static __device__ float g_h0[400000];
static __device__ float g_x1[800000];
static __device__ float g_x2[1600000];
static __device__ float g_x3[3200000];
static __device__ float g_x4[6400000];
static __device__ float g_h5[3200000];
static __device__ float g_h6[1600000];

static __device__ uint4 g_bufA[400000];
static __device__ uint4 g_bufB[400000];

static __device__ int   g_deg[N_NODES];
static __device__ int   g_row[N_NODES];
static __device__ int   g_cur[N_NODES];
static __device__ int   g_part[512];
static __device__ int   g_srcs[3500000];
static __device__ float g_invdeg[N_NODES];

static __device__ unsigned g_maxx, g_minx, g_maxy, g_miny, g_maxrx, g_maxry, g_maxa;
static __device__ float g_sumx, g_sumy;

// global barrier state
static __device__ unsigned g_barc = 0;
static __device__ volatile unsigned g_gen = 0;

// ---------------- helpers ----------------
__device__ __forceinline__ unsigned f2o(float f) {
    unsigned u = __float_as_uint(f);
    return (u & 0x80000000u) ? ~u : (u | 0x80000000u);
}
__device__ __forceinline__ float o2f(unsigned u) {
    return (u & 0x80000000u) ? __uint_as_float(u & 0x7FFFFFFFu) : __uint_as_float(~u);
}
__device__ __forceinline__ u64 pack2(float a, float b) {
    u64 r; asm("mov.b64 %0,{%1,%2};" : "=l"(r) : "f"(a), "f"(b)); return r;
}
__device__ __forceinline__ void unpack2(u64 v, float& a, float& b) {
    asm("mov.b64 {%0,%1},%2;" : "=f"(a), "=f"(b) : "l"(v));
}
__device__ __forceinline__ u64 fma2(u64 a, u64 b, u64 c) {
    u64 d; asm("fma.rn.f32x2 %0,%1,%2,%3;" : "=l"(d) : "l"(a), "l"(b), "l"(c)); return d;
}
__device__ __forceinline__ float tanh_fast(float x) {
    float y; asm("tanh.approx.f32 %0,%1;" : "=f"(y) : "f"(x)); return y;
}

// grid-wide barrier (all blocks resident by construction)
__device__ __forceinline__ void grid_bar() {
    __syncthreads();
    if (threadIdx.x == 0) {
        unsigned gen = g_gen;
        __threadfence();                       // release all prior writes
        unsigned old = atomicAdd(&g_barc, 1);
        if (old == gridDim.x - 1) {
            g_barc = 0;
            __threadfence();
            g_gen = gen + 1;
        } else {
            while (g_gen == gen) { __nanosleep(64); }
        }
        __threadfence();                       // acquire
    }
    __syncthreads();
}

__device__ __forceinline__ float blockSum(float v, float* s) {
    int t = threadIdx.x;
    s[t] = v; __syncthreads();
    for (int o = 128; o > 0; o >>= 1) { if (t < o) s[t] += s[t + o]; __syncthreads(); }
    float r = s[0]; __syncthreads();
    return r;
}
__device__ __forceinline__ float blockMax(float v, float* s) {
    int t = threadIdx.x;
    s[t] = v; __syncthreads();
    for (int o = 128; o > 0; o >>= 1) { if (t < o) s[t] = fmaxf(s[t], s[t + o]); __syncthreads(); }
    float r = s[0]; __syncthreads();
    return r;
}
__device__ __forceinline__ float blockMin(float v, float* s) {
    int t = threadIdx.x;
    s[t] = v; __syncthreads();
    for (int o = 128; o > 0; o >>= 1) { if (t < o) s[t] = fminf(s[t], s[t + o]); __syncthreads(); }
    float r = s[0]; __syncthreads();
    return r;
}

// ---------------- setup kernels (unchanged from R14) ----------------
__global__ void k_zero_init() {
    int i = blockIdx.x * blockDim.x + threadIdx.x;
    if (i < N_NODES) g_deg[i] = 0;
    if (i == 0) {
        g_maxx = 0u; g_maxy = 0u; g_maxrx = 0u; g_maxry = 0u; g_maxa = 0u;
        g_minx = 0xFFFFFFFFu; g_miny = 0xFFFFFFFFu;
        g_sumx = 0.f; g_sumy = 0.f;
    }
}

__global__ void __launch_bounds__(256) k_count_stats(const int* __restrict__ dst,
                                                     const float* __restrict__ x) {
    __shared__ float s[256];
    int e4 = blockIdx.x * 256 + threadIdx.x;
    if (e4 * 4 < N_EDGES) {
        int4 d = ((const int4*)dst)[e4];
        atomicAdd(&g_deg[d.x], 1);
        atomicAdd(&g_deg[d.y], 1);
        atomicAdd(&g_deg[d.z], 1);
        atomicAdd(&g_deg[d.w], 1);
    }
    if (blockIdx.x >= NBLK_N) return;

    int n = blockIdx.x * 256 + threadIdx.x;
    float X = -3.402823466e38f, Y = -3.402823466e38f, A = -3.402823466e38f;
    float Xm = 3.402823466e38f, Ym = 3.402823466e38f;
    float sx = 0.f, sy = 0.f, RX = -3.402823466e38f, RY = -3.402823466e38f;
    const float th = (float)(M_PI / 2.0);
    const float c = cosf(th), sn = sinf(th);
    if (n < N_NODES) {
        float px = x[n * 3 + 0], py = x[n * 3 + 1], pa = x[n * 3 + 2];
        X = px; Xm = px; Y = py; Ym = py; A = pa;
        sx = px; sy = py;
        RX = c * px - sn * py;
        RY = sn * px + c * py;
    }
    float bs;
    bs = blockMax(X, s);  if (threadIdx.x == 0) atomicMax(&g_maxx, f2o(bs));
    bs = blockMin(Xm, s); if (threadIdx.x == 0) atomicMin(&g_minx, f2o(bs));
    bs = blockMax(Y, s);  if (threadIdx.x == 0) atomicMax(&g_maxy, f2o(bs));
    bs = blockMin(Ym, s); if (threadIdx.x == 0) atomicMin(&g_miny, f2o(bs));
    bs = blockMax(RX, s); if (threadIdx.x == 0) atomicMax(&g_maxrx, f2o(bs));
    bs = blockMax(RY, s); if (threadIdx.x == 0) atomicMax(&g_maxry, f2o(bs));
    bs = blockMax(A, s);  if (threadIdx.x == 0) atomicMax(&g_maxa, f2o(bs));
    bs = blockSum(sx, s); if (threadIdx.x == 0) atomicAdd(&g_sumx, bs);
    bs = blockSum(sy, s); if (threadIdx.x == 0) atomicAdd(&g_sumy, bs);
}

__global__ void __launch_bounds__(256) k_norm_scan1(const float* __restrict__ x) {
    __shared__ int s[256];
    int t = threadIdx.x;
    int i = blockIdx.x * 256 + t;
    s[t] = (i < N_NODES) ? ((g_deg[i] + 3) & ~3) : 0;
    __syncthreads();
    for (int o = 128; o > 0; o >>= 1) { if (t < o) s[t] += s[t + o]; __syncthreads(); }
    if (t == 0) g_part[blockIdx.x] = s[0];
    if (i >= N_NODES) return;
    float maxx = o2f(g_maxx), minx = o2f(g_minx);
    float maxy = o2f(g_maxy), miny = o2f(g_miny);
    float maxa = o2f(g_maxa);
    float meanx = g_sumx / (float)N_NODES, meany = g_sumy / (float)N_NODES;
    bool cond = (maxy - miny) > (maxx - minx);
    const float th = (float)(M_PI / 2.0);
    const float c = cosf(th), sn = sinf(th);
    float px = x[i * 3 + 0], py = x[i * 3 + 1], pa = x[i * 3 + 2];
    float cx, cy, mnx, mny, mxx, mxy;
    if (cond) {
        cx = c * px - sn * py;
        cy = sn * px + c * py;
        mnx = c * meanx - sn * meany;
        mny = sn * meanx + c * meany;
        mxx = o2f(g_maxrx);
        mxy = o2f(g_maxry);
    } else {
        cx = px; cy = py; mnx = meanx; mny = meany; mxx = maxx; mxy = maxy;
    }
    float4 o;
    o.x = (cx - mnx) / mxx;
    o.y = (cy - mny) / mxy;
    o.z = pa / maxa;
    o.w = 0.f;
    ((float4*)g_h0)[i] = o;
}

__global__ void __launch_bounds__(256) k_scan3() {
    __shared__ int s[256];
    __shared__ int sp2[512];
    int t = threadIdx.x;
    int p0 = (t < NBLK_N && t < blockIdx.x) ? g_part[t] : 0;
    int p1 = (t + 256 < NBLK_N && t + 256 < (int)blockIdx.x) ? g_part[t + 256] : 0;
    sp2[t] = p0; sp2[t + 256] = p1;
    __syncthreads();
    for (int o = 256; o > 0; o >>= 1) { if (t < o) sp2[t] += sp2[t + o]; __syncthreads(); }
    int bprefix = sp2[0];

    int i = blockIdx.x * 256 + t;
    int dreal = (i < N_NODES) ? g_deg[i] : 0;
    int v = (dreal + 3) & ~3;
    s[t] = v; __syncthreads();
    for (int o = 1; o < 256; o <<= 1) {
        int a = (t >= o) ? s[t - o] : 0;
        __syncthreads();
        s[t] += a;
        __syncthreads();
    }
    if (i < N_NODES) {
        int ex = bprefix + s[t] - v;
        g_row[i] = ex;
        g_cur[i] = ex;
        g_invdeg[i] = 1.0f / (float)(dreal > 0 ? dreal : 1);
    }
}

__global__ void k_scatter(const int* __restrict__ src, const int* __restrict__ dst) {
    int e4 = blockIdx.x * blockDim.x + threadIdx.x;
    if (e4 * 4 < N_EDGES) {
        int4 d = ((const int4*)dst)[e4];
        int4 sv = ((const int4*)src)[e4];
        int p0 = atomicAdd(&g_cur[d.x], 1); g_srcs[p0] = sv.x;
        int p1 = atomicAdd(&g_cur[d.y], 1); g_srcs[p1] = sv.y;
        int p2 = atomicAdd(&g_cur[d.z], 1); g_srcs[p2] = sv.z;
        int p3 = atomicAdd(&g_cur[d.w], 1); g_srcs[p3] = sv.w;
    }
}

// ---------------- gather helpers (L1-bypass) ----------------
template <int TPN>
__device__ __forceinline__ void gacc_f32(const uint4* __restrict__ gsrc, int idx, int q,
                                         float (&acc)[4]) {
    uint4 v = __ldcg(&gsrc[(size_t)idx * TPN + q]);
    acc[0] += __uint_as_float(v.x);
    acc[1] += __uint_as_float(v.y);
    acc[2] += __uint_as_float(v.z);
    acc[3] += __uint_as_float(v.w);
}
template <int TPN>
__device__ __forceinline__ void gacc_f16(const uint4* __restrict__ gsrc, int idx, int q,
                                         float (&acc)[8]) {
    uint4 v = __ldcg(&gsrc[(size_t)idx * TPN + q]);
    float2 f0 = __half22float2(*(const __half2*)&v.x);
    float2 f1 = __half22float2(*(const __half2*)&v.y);
    float2 f2 = __half22float2(*(const __half2*)&v.z);
    float2 f3 = __half22float2(*(const __half2*)&v.w);
    acc[0] += f0.x; acc[1] += f0.y;
    acc[2] += f1.x; acc[3] += f1.y;
    acc[4] += f2.x; acc[5] += f2.y;
    acc[6] += f3.x; acc[7] += f3.y;
}
template <int TPN>
__device__ __forceinline__ void gacc_i8(const uint4* __restrict__ gsrc, int idx, int q,
                                        int (&acc)[16]) {
    uint4 v = __ldcg(&gsrc[(size_t)idx * TPN + q]);
    int w[4] = {(int)v.x, (int)v.y, (int)v.z, (int)v.w};
#pragma unroll
    for (int wi = 0; wi < 4; wi++) {
        acc[wi * 4 + 0] = __dp4a(w[wi], 0x00000001, acc[wi * 4 + 0]);
        acc[wi * 4 + 1] = __dp4a(w[wi], 0x00000100, acc[wi * 4 + 1]);
        acc[wi * 4 + 2] = __dp4a(w[wi], 0x00010000, acc[wi * 4 + 2]);
        acc[wi * 4 + 3] = __dp4a(w[wi], 0x01000000, acc[wi * 4 + 3]);
    }
}

// ---------------- one SAGE layer inside the persistent kernel ----------------
template <int TPN, int ES, int GM, int FI, int FIS, int FO, bool RES, bool PRE, int GHM,
          int XFI, int XFO, bool MLPH>
__device__ void sage_layer(const uint4* __restrict__ gsrc,
                           const float* __restrict__ xin,
                           const float* __restrict__ res,
                           float* __restrict__ xout,
                           const float* __restrict__ wl,
                           const float* __restrict__ bl,
                           const float* __restrict__ wr,
                           const float* __restrict__ xwl,
                           void* __restrict__ ghout,
                           const float* w1, const float* b1,
                           const float* w2, const float* b2,
                           const float* w3, const float* b3,
                           float* __restrict__ mout,
                           float* s_mean, float* s_wl, float* s_wr, float* s_bl,
                           float* s_out, float* s_xwl, float* s_mlp) {
    static_assert(TPN * ES == 4, "4-thread node groups");
    constexpr int ELEM = (GM == GM_F32) ? 4 : (GM == GM_F16 ? 8 : 16);
    constexpr int HD = TPN * ELEM;
    constexpr int NB = 64;
    constexpr bool SOUT = (XFO > 0) || MLPH;
    int t = threadIdx.x;

    // weights: load ONCE per block for the whole layer
    if constexpr (!PRE) { for (int i = t; i < FI * FO; i += 256) s_wl[i] = wl[i]; }
    for (int i = t; i < FI * FO; i += 256) s_wr[i] = wr[i];
    if constexpr (XFO > 0) { for (int i = t; i < XFI * XFO; i += 256) s_xwl[i] = xwl[i]; }
    if constexpr (MLPH) {
        if (t < 256) s_mlp[t] = w1[t];                      // w1 @0
        if (t < 32) { s_mlp[256 + t] = b1[t]; s_mlp[816 + t] = w3[t]; }  // b1 @256, w3 @816
        for (int i = t; i < 512; i += 256) s_mlp[288 + i] = w2[i];       // w2 @288
        if (t < 16) s_mlp[800 + t] = b2[t];                 // b2 @800
        if (t < 2) s_mlp[848 + t] = b3[t];                  // b3 @848
    }
    if (t < FO) s_bl[t] = bl[t];
    __syncthreads();

    for (int tile = blockIdx.x; tile < NBLK_S; tile += gridDim.x) {
        int nbase = tile * NB;

        // ---- phase 1: mean aggregation ----
        {
            int nl = t >> 2;
            int sub = t & 3;
            int q = sub % TPN;
            int es = sub / TPN;
            int n = nbase + nl;

            float accf[(GM == GM_I8) ? 1 : ELEM];
            int acci[(GM == GM_I8) ? 16 : 1];
#pragma unroll
            for (int k = 0; k < ((GM == GM_I8) ? 1 : ELEM); k++) accf[k] = 0.f;
#pragma unroll
            for (int k = 0; k < ((GM == GM_I8) ? 16 : 1); k++) acci[k] = 0;

            auto do_edge = [&](int idx) {
                if constexpr (GM == GM_F32) gacc_f32<TPN>(gsrc, idx, q, (float(&)[4])accf);
                else if constexpr (GM == GM_F16) gacc_f16<TPN>(gsrc, idx, q, (float(&)[8])accf);
                else gacc_i8<TPN>(gsrc, idx, q, acci);
            };

            if (n < N_NODES) {
                int start = g_row[n];
                int dg = g_deg[n];
                const int* sp = g_srcs + start;
                int Q = dg >> 2;
                int nq = (Q > es) ? ((Q - es + ES - 1) / ES) : 0;
                if (nq > 0) {
                    const int4* qp = (const int4*)sp + es;
                    int4 c0 = __ldcg(qp);
                    int4 c1;
                    if (nq > 1) c1 = __ldcg(qp + ES);
                    for (int i2 = 2; i2 < nq; i2++) {
                        int4 nx = __ldcg(qp + (size_t)i2 * ES);
                        do_edge(c0.x); do_edge(c0.y); do_edge(c0.z); do_edge(c0.w);
                        c0 = c1; c1 = nx;
                    }
                    do_edge(c0.x); do_edge(c0.y); do_edge(c0.z); do_edge(c0.w);
                    if (nq > 1) { do_edge(c1.x); do_edge(c1.y); do_edge(c1.z); do_edge(c1.w); }
                }
                if (es == 0) {
                    for (int e = Q * 4; e < dg; e++) do_edge(sp[e]);
                }
            }
            if constexpr (GM == GM_I8) {
#pragma unroll
                for (int off = TPN; off < 4; off <<= 1)
#pragma unroll
                    for (int k = 0; k < 16; k++)
                        acci[k] += __shfl_xor_sync(0xffffffffu, acci[k], off);
            } else {
#pragma unroll
                for (int off = TPN; off < 4; off <<= 1)
#pragma unroll
                    for (int k = 0; k < ELEM; k++)
                        accf[k] += __shfl_xor_sync(0xffffffffu, accf[k], off);
            }
            if (n < N_NODES && es == 0) {
                float inv = g_invdeg[n];
                if constexpr (GM == GM_I8) {
                    float sc = inv * (1.0f / 127.0f);
#pragma unroll
                    for (int k = 0; k < 16; k++)
                        s_mean[nl * HD + q * 16 + k] = (float)acci[k] * sc;
                } else {
#pragma unroll
                    for (int k = 0; k < ELEM; k++)
                        s_mean[nl * HD + q * ELEM + k] = accf[k] * inv;
                }
            }
        }
        __syncthreads();

        // ---- phase 2 ----
        constexpr int PAIRS = FO / 2;
        constexpr int NP2 = 256 / PAIRS;
        for (int p = 0; p < NB; p += NP2) {
            int nl2 = p + t / PAIRS;
            int fo2 = t % PAIRS;
            if (nl2 < NB) {
                int n = nbase + nl2;
                if (n < N_NODES) {
                    float b0 = s_bl[2 * fo2], b1v = s_bl[2 * fo2 + 1];
                    if constexpr (PRE) {
                        b0 += s_mean[nl2 * HD + 2 * fo2];
                        b1v += s_mean[nl2 * HD + 2 * fo2 + 1];
                    }
                    u64 v = pack2(b0, b1v);
                    const float* xr = xin + (size_t)n * FIS;
#pragma unroll
                    for (int i = 0; i < FI; i++) {
                        float xi = xr[i];
                        u64 xv = pack2(xi, xi);
                        v = fma2(xv, ((const u64*)s_wr)[i * PAIRS + fo2], v);
                        if constexpr (!PRE) {
                            float mi = s_mean[nl2 * HD + i];
                            u64 mv = pack2(mi, mi);
                            v = fma2(mv, ((const u64*)s_wl)[i * PAIRS + fo2], v);
                        }
                    }
                    float r0, r1; unpack2(v, r0, r1);
                    r0 = tanh_fast(r0); r1 = tanh_fast(r1);
                    if constexpr (RES) {
                        float2 rr = ((const float2*)res)[(size_t)n * PAIRS + fo2];
                        r0 += rr.x; r1 += rr.y;
                    }
                    if constexpr (!MLPH) {
                        ((float2*)xout)[(size_t)n * PAIRS + fo2] = make_float2(r0, r1);
                    }
                    if constexpr (GHM == GH_F16) {
                        ((__half2*)ghout)[(size_t)n * PAIRS + fo2] =
                            __float22half2_rn(make_float2(r0, r1));
                    } else if constexpr (GHM == GH_I8) {
                        char2 cc;
                        cc.x = (char)__float2int_rn(r0 * 127.0f);
                        cc.y = (char)__float2int_rn(r1 * 127.0f);
                        ((char2*)ghout)[(size_t)n * PAIRS + fo2] = cc;
                    }
                    if constexpr (SOUT) {
                        s_out[nl2 * FO + 2 * fo2] = r0;
                        s_out[nl2 * FO + 2 * fo2 + 1] = r1;
                    }
                }
            }
        }

        // ---- phase 3a: y = out @ xwl -> fp16 next-layer gather rows ----
        if constexpr (XFO > 0) {
            __syncthreads();
            for (int base = 0; base < NB * XFO; base += 256) {
                int idx2 = base + t;
                if (idx2 < NB * XFO) {
                    int nl = idx2 / XFO, fo = idx2 % XFO;
                    int n = nbase + nl;
                    if (n < N_NODES) {
                        float v = 0.f;
#pragma unroll
                        for (int i = 0; i < XFI; i++)
                            v += s_out[nl * XFI + i] * s_xwl[i * XFO + fo];
                        ((__half*)ghout)[(size_t)n * XFO + fo] = __float2half_rn(v);
                    }
                }
            }
        }

        // ---- phase 3b: fused MLP head + softmax ----
        if constexpr (MLPH) {
            __syncthreads();
            if (t < NB) {
                int n = nbase + t;
                if (n < N_NODES) {
                    const float* m_w1 = s_mlp;
                    const float* m_b1 = s_mlp + 256;
                    const float* m_w2 = s_mlp + 288;
                    const float* m_b2 = s_mlp + 800;
                    const float* m_w3 = s_mlp + 816;
                    const float* m_b3 = s_mlp + 848;
                    float in8[8];
#pragma unroll
                    for (int i = 0; i < 8; i++) in8[i] = s_out[t * 8 + i];
                    float a[32];
#pragma unroll
                    for (int j = 0; j < 32; j++) {
                        float v = m_b1[j];
#pragma unroll
                        for (int i = 0; i < 8; i++) v += in8[i] * m_w1[i * 32 + j];
                        a[j] = tanh_fast(v);
                    }
                    float bb[16];
#pragma unroll
                    for (int j = 0; j < 16; j++) {
                        float v = m_b2[j];
#pragma unroll
                        for (int i = 0; i < 32; i++) v += a[i] * m_w2[i * 16 + j];
                        bb[j] = tanh_fast(v);
                    }
                    float c0 = m_b3[0], c1 = m_b3[1];
#pragma unroll
                    for (int i = 0; i < 16; i++) { c0 += bb[i] * m_w3[i * 2 + 0]; c1 += bb[i] * m_w3[i * 2 + 1]; }
                    float m = fmaxf(c0, c1);
                    float e0 = __expf(c0 - m), e1 = __expf(c1 - m);
                    float inv = 1.f / (e0 + e1);
                    ((float2*)mout)[n] = make_float2(e0 * inv, e1 * inv);
                }
            }
        }
        __syncthreads();   // s_mean/s_out reused by next tile
    }
}

// ---------------- persistent network kernel ----------------
struct NetArgs {
    const float* cwl[7]; const float* cbl[7]; const float* cwr[7];
    const float* w1; const float* b1;
    const float* w2; const float* b2;
    const float* w3; const float* b3;
    float* out;
};

__global__ void __launch_bounds__(256) k_net(NetArgs a) {
    __shared__ __align__(16) float s_mean[64 * 32];
    __shared__ __align__(16) float s_wl[32 * 64];
    __shared__ __align__(16) float s_wr[32 * 64];
    __shared__ float s_bl[64];
    __shared__ __align__(16) float s_out[64 * 64];
    __shared__ __align__(16) float s_xwl[64 * 32];
    __shared__ __align__(16) float s_mlp[850];

    // L1: 3->8 gather h0 fp32
    sage_layer<1, 4, GM_F32, 3, 4, 8, false, false, GH_F16, 0, 0, false>(
        (const uint4*)g_h0, g_h0, nullptr, g_x1, a.cwl[0], a.cbl[0], a.cwr[0], nullptr,
        (void*)g_bufB, nullptr, nullptr, nullptr, nullptr, nullptr, nullptr, nullptr,
        s_mean, s_wl, s_wr, s_bl, s_out, s_xwl, s_mlp);
    grid_bar();
    // L2: 8->16 gather fp16(B)
    sage_layer<1, 4, GM_F16, 8, 8, 16, false, false, GH_I8, 0, 0, false>(
        g_bufB, g_x1, nullptr, g_x2, a.cwl[1], a.cbl[1], a.cwr[1], nullptr,
        (void*)g_bufA, nullptr, nullptr, nullptr, nullptr, nullptr, nullptr, nullptr,
        s_mean, s_wl, s_wr, s_bl, s_out, s_xwl, s_mlp);
    grid_bar();
    // L3: 16->32 gather int8(A)
    sage_layer<1, 4, GM_I8, 16, 16, 32, false, false, GH_I8, 0, 0, false>(
        g_bufA, g_x2, nullptr, g_x3, a.cwl[2], a.cbl[2], a.cwr[2], nullptr,
        (void*)g_bufB, nullptr, nullptr, nullptr, nullptr, nullptr, nullptr, nullptr,
        s_mean, s_wl, s_wr, s_bl, s_out, s_xwl, s_mlp);
    grid_bar();
    // L4: 32->64 gather int8(B) ; y5 = x4@wl5 fp16 -> A
    sage_layer<2, 2, GM_I8, 32, 32, 64, false, false, GH_NONE, 64, 32, false>(
        g_bufB, g_x3, nullptr, g_x4, a.cwl[3], a.cbl[3], a.cwr[3], a.cwl[4],
        (void*)g_bufA, nullptr, nullptr, nullptr, nullptr, nullptr, nullptr, nullptr,
        s_mean, s_wl, s_wr, s_bl, s_out, s_xwl, s_mlp);
    grid_bar();
    // L5: (PRE) gather y5 fp16(A), self x4, res x3 ; y6 = h5@wl6 -> B
    sage_layer<4, 1, GM_F16, 64, 64, 32, true, true, GH_NONE, 32, 16, false>(
        g_bufA, g_x4, g_x3, g_h5, a.cwl[4], a.cbl[4], a.cwr[4], a.cwl[5],
        (void*)g_bufB, nullptr, nullptr, nullptr, nullptr, nullptr, nullptr, nullptr,
        s_mean, s_wl, s_wr, s_bl, s_out, s_xwl, s_mlp);
    grid_bar();
    // L6: (PRE) gather y6 fp16(B), self h5, res x2 ; y7 = h6@wl7 -> A
    sage_layer<2, 2, GM_F16, 32, 32, 16, true, true, GH_NONE, 16, 8, false>(
        g_bufB, g_h5, g_x2, g_h6, a.cwl[5], a.cbl[5], a.cwr[5], a.cwl[6],
        (void*)g_bufA, nullptr, nullptr, nullptr, nullptr, nullptr, nullptr, nullptr,
        s_mean, s_wl, s_wr, s_bl, s_out, s_xwl, s_mlp);
    grid_bar();
    // L7: (PRE) gather y7 fp16(A), self h6, res x1 ; fused MLP head -> out
    sage_layer<1, 4, GM_F16, 16, 16, 8, true, true, GH_NONE, 0, 0, true>(
        g_bufA, g_h6, g_x1, nullptr, a.cwl[6], a.cbl[6], a.cwr[6], nullptr,
        nullptr, a.w1, a.b1, a.w2, a.b2, a.w3, a.b3, a.out,
        s_mean, s_wl, s_wr, s_bl, s_out, s_xwl, s_mlp);
}

// ---------------- launch ----------------
extern "C" void kernel_launch(void* const* d_in, const int* in_sizes, int n_in,
                              void* d_out, int out_size) {
    const float* x = (const float*)d_in[0];
    const int* ei = (const int*)d_in[1];
    const int* src = ei;
    const int* dst = ei + N_EDGES;

    NetArgs a;
    for (int l = 0; l < 7; l++) {
        a.cwl[l] = (const float*)d_in[2 + 3 * l + 0];
        a.cbl[l] = (const float*)d_in[2 + 3 * l + 1];
        a.cwr[l] = (const float*)d_in[2 + 3 * l + 2];
    }
    a.w1 = (const float*)d_in[23];
    a.b1 = (const float*)d_in[24];
    a.w2 = (const float*)d_in[25];
    a.b2 = (const float*)d_in[26];
    a.w3 = (const float*)d_in[27];
    a.b3 = (const float*)d_in[28];
    a.out = (float*)d_out;

    // persistent grid: guaranteed co-resident (deadlock-free software barrier)
    int dev = 0;
    cudaGetDevice(&dev);
    int nsm = 148;
    cudaDeviceGetAttribute(&nsm, cudaDevAttrMultiProcessorCount, dev);
    int occ = 1;
    cudaOccupancyMaxActiveBlocksPerMultiprocessor(&occ, k_net, 256, 0);
    if (occ < 1) occ = 1;
    int grid = nsm * occ;
    if (grid > NBLK_S) grid = NBLK_S;

    // setup + CSR build
    k_zero_init<<<NBLK_N, 256>>>();
    k_count_stats<<<NBLK_E4, 256>>>(dst, x);
    k_norm_scan1<<<NBLK_N, 256>>>(x);
    k_scan3<<<NBLK_N, 256>>>();
    k_scatter<<<NBLK_E4, 256>>>(src, dst);

    // all 7 SAGE layers + MLP head in one persistent kernel
    k_net<<<grid, 256>>>(a);
}

// round 16
// speedup vs baseline: 1.0432x; 1.0432x over previous
#include <cuda_runtime.h>
#include <cuda_fp16.h>
#include <math.h>

#define N_NODES 100000
#define N_EDGES 3200000
#define NBLK_N 391
#define NBLK_E4 3125

typedef unsigned long long u64;

#define GM_F32 0
#define GM_F16 1
#define GM_I8  2
#define GH_NONE 0
#define GH_F16  1
#define GH_I8   2

// ---------------- static device scratch (allocation-free) ----------------
static __device__ float g_h0[400000];      // fp32, stride 4 (L1 gather; fp16 would overflow)
static __device__ float g_x1[800000];
static __device__ float g_x2[1600000];
static __device__ float g_x3[3200000];
static __device__ float g_x4[6400000];
static __device__ float g_h5[3200000];
static __device__ float g_h6[1600000];

static __device__ uint4 g_bufA[400000];
static __device__ uint4 g_bufB[400000];

static __device__ int   g_deg[N_NODES];
static __device__ int   g_row[N_NODES];
static __device__ int   g_cur[N_NODES];
static __device__ int   g_part[512];
static __device__ int   g_srcs[3500000];   // padded CSR: rows 4-aligned
static __device__ float g_invdeg[N_NODES];

static __device__ unsigned g_maxx, g_minx, g_maxy, g_miny, g_maxrx, g_maxry, g_maxa;
static __device__ float g_sumx, g_sumy;

// ---------------- helpers ----------------
__device__ __forceinline__ unsigned f2o(float f) {
    unsigned u = __float_as_uint(f);
    return (u & 0x80000000u) ? ~u : (u | 0x80000000u);
}
__device__ __forceinline__ float o2f(unsigned u) {
    return (u & 0x80000000u) ? __uint_as_float(u & 0x7FFFFFFFu) : __uint_as_float(~u);
}
__device__ __forceinline__ u64 pack2(float a, float b) {
    u64 r; asm("mov.b64 %0,{%1,%2};" : "=l"(r) : "f"(a), "f"(b)); return r;
}
__device__ __forceinline__ void unpack2(u64 v, float& a, float& b) {
    asm("mov.b64 {%0,%1},%2;" : "=f"(a), "=f"(b) : "l"(v));
}
__device__ __forceinline__ u64 fma2(u64 a, u64 b, u64 c) {
    u64 d; asm("fma.rn.f32x2 %0,%1,%2,%3;" : "=l"(d) : "l"(a), "l"(b), "l"(c)); return d;
}
__device__ __forceinline__ float tanh_fast(float x) {
    float y; asm("tanh.approx.f32 %0,%1;" : "=f"(y) : "f"(x)); return y;
}

__device__ __forceinline__ float blockSum(float v, float* s) {
    int t = threadIdx.x;
    s[t] = v; __syncthreads();
    for (int o = 128; o > 0; o >>= 1) { if (t < o) s[t] += s[t + o]; __syncthreads(); }
    float r = s[0]; __syncthreads();
    return r;
}
__device__ __forceinline__ float blockMax(float v, float* s) {
    int t = threadIdx.x;
    s[t] = v; __syncthreads();
    for (int o = 128; o > 0; o >>= 1) { if (t < o) s[t] = fmaxf(s[t], s[t + o]); __syncthreads(); }
    float r = s[0]; __syncthreads();
    return r;
}
__device__ __forceinline__ float blockMin(float v, float* s) {
    int t = threadIdx.x;
    s[t] = v; __syncthreads();
    for (int o = 128; o > 0; o >>= 1) { if (t < o) s[t] = fminf(s[t], s[t + o]); __syncthreads(); }
    float r = s[0]; __syncthreads();
    return r;
}

// ---------------- setup kernels ----------------
__global__ void k_zero_init() {
    int i = blockIdx.x * blockDim.x + threadIdx.x;
    if (i < N_NODES) g_deg[i] = 0;
    if (i == 0) {
        g_maxx = 0u; g_maxy = 0u; g_maxrx = 0u; g_maxry = 0u; g_maxa = 0u;
        g_minx = 0xFFFFFFFFu; g_miny = 0xFFFFFFFFu;
        g_sumx = 0.f; g_sumy = 0.f;
    }
}

__global__ void __launch_bounds__(256) k_count_stats(const int* __restrict__ dst,
                                                     const float* __restrict__ x) {
    __shared__ float s[256];
    int e4 = blockIdx.x * 256 + threadIdx.x;
    if (e4 * 4 < N_EDGES) {
        int4 d = ((const int4*)dst)[e4];
        atomicAdd(&g_deg[d.x], 1);
        atomicAdd(&g_deg[d.y], 1);
        atomicAdd(&g_deg[d.z], 1);
        atomicAdd(&g_deg[d.w], 1);
    }
    if (blockIdx.x >= NBLK_N) return;

    int n = blockIdx.x * 256 + threadIdx.x;
    float X = -3.402823466e38f, Y = -3.402823466e38f, A = -3.402823466e38f;
    float Xm = 3.402823466e38f, Ym = 3.402823466e38f;
    float sx = 0.f, sy = 0.f, RX = -3.402823466e38f, RY = -3.402823466e38f;
    const float th = (float)(M_PI / 2.0);
    const float c = cosf(th), sn = sinf(th);
    if (n < N_NODES) {
        float px = x[n * 3 + 0], py = x[n * 3 + 1], pa = x[n * 3 + 2];
        X = px; Xm = px; Y = py; Ym = py; A = pa;
        sx = px; sy = py;
        RX = c * px - sn * py;
        RY = sn * px + c * py;
    }
    float bs;
    bs = blockMax(X, s);  if (threadIdx.x == 0) atomicMax(&g_maxx, f2o(bs));
    bs = blockMin(Xm, s); if (threadIdx.x == 0) atomicMin(&g_minx, f2o(bs));
    bs = blockMax(Y, s);  if (threadIdx.x == 0) atomicMax(&g_maxy, f2o(bs));
    bs = blockMin(Ym, s); if (threadIdx.x == 0) atomicMin(&g_miny, f2o(bs));
    bs = blockMax(RX, s); if (threadIdx.x == 0) atomicMax(&g_maxrx, f2o(bs));
    bs = blockMax(RY, s); if (threadIdx.x == 0) atomicMax(&g_maxry, f2o(bs));
    bs = blockMax(A, s);  if (threadIdx.x == 0) atomicMax(&g_maxa, f2o(bs));
    bs = blockSum(sx, s); if (threadIdx.x == 0) atomicAdd(&g_sumx, bs);
    bs = blockSum(sy, s); if (threadIdx.x == 0) atomicAdd(&g_sumy, bs);
}

__global__ void __launch_bounds__(256) k_norm_scan1(const float* __restrict__ x) {
    __shared__ int s[256];
    int t = threadIdx.x;
    int i = blockIdx.x * 256 + t;
    s[t] = (i < N_NODES) ? ((g_deg[i] + 3) & ~3) : 0;
    __syncthreads();
    for (int o = 128; o > 0; o >>= 1) { if (t < o) s[t] += s[t + o]; __syncthreads(); }
    if (t == 0) g_part[blockIdx.x] = s[0];
    if (i >= N_NODES) return;
    float maxx = o2f(g_maxx), minx = o2f(g_minx);
    float maxy = o2f(g_maxy), miny = o2f(g_miny);
    float maxa = o2f(g_maxa);
    float meanx = g_sumx / (float)N_NODES, meany = g_sumy / (float)N_NODES;
    bool cond = (maxy - miny) > (maxx - minx);
    const float th = (float)(M_PI / 2.0);
    const float c = cosf(th), sn = sinf(th);
    float px = x[i * 3 + 0], py = x[i * 3 + 1], pa = x[i * 3 + 2];
    float cx, cy, mnx, mny, mxx, mxy;
    if (cond) {
        cx = c * px - sn * py;
        cy = sn * px + c * py;
        mnx = c * meanx - sn * meany;
        mny = sn * meanx + c * meany;
        mxx = o2f(g_maxrx);
        mxy = o2f(g_maxry);
    } else {
        cx = px; cy = py; mnx = meanx; mny = meany; mxx = maxx; mxy = maxy;
    }
    float4 o;
    o.x = (cx - mnx) / mxx;
    o.y = (cy - mny) / mxy;
    o.z = pa / maxa;
    o.w = 0.f;
    ((float4*)g_h0)[i] = o;
}

__global__ void __launch_bounds__(256) k_scan3() {
    __shared__ int s[256];
    __shared__ int sp2[512];
    int t = threadIdx.x;
    int p0 = (t < NBLK_N && t < blockIdx.x) ? g_part[t] : 0;
    int p1 = (t + 256 < NBLK_N && t + 256 < (int)blockIdx.x) ? g_part[t + 256] : 0;
    sp2[t] = p0; sp2[t + 256] = p1;
    __syncthreads();
    for (int o = 256; o > 0; o >>= 1) { if (t < o) sp2[t] += sp2[t + o]; __syncthreads(); }
    int bprefix = sp2[0];

    int i = blockIdx.x * 256 + t;
    int dreal = (i < N_NODES) ? g_deg[i] : 0;
    int v = (dreal + 3) & ~3;
    s[t] = v; __syncthreads();
    for (int o = 1; o < 256; o <<= 1) {
        int a = (t >= o) ? s[t - o] : 0;
        __syncthreads();
        s[t] += a;
        __syncthreads();
    }
    if (i < N_NODES) {
        int ex = bprefix + s[t] - v;
        g_row[i] = ex;
        g_cur[i] = ex;
        g_invdeg[i] = 1.0f / (float)(dreal > 0 ? dreal : 1);
    }
}

__global__ void k_scatter(const int* __restrict__ src, const int* __restrict__ dst) {
    int e4 = blockIdx.x * blockDim.x + threadIdx.x;
    if (e4 * 4 < N_EDGES) {
        int4 d = ((const int4*)dst)[e4];
        int4 sv = ((const int4*)src)[e4];
        int p0 = atomicAdd(&g_cur[d.x], 1); g_srcs[p0] = sv.x;
        int p1 = atomicAdd(&g_cur[d.y], 1); g_srcs[p1] = sv.y;
        int p2 = atomicAdd(&g_cur[d.z], 1); g_srcs[p2] = sv.z;
        int p3 = atomicAdd(&g_cur[d.w], 1); g_srcs[p3] = sv.w;
    }
}

// ---------------- gather helpers (L1-bypass) ----------------
template <int TPN>
__device__ __forceinline__ void gacc_f32(const uint4* __restrict__ gsrc, int idx, int q,
                                         float (&acc)[4]) {
    uint4 v = __ldcg(&gsrc[(size_t)idx * TPN + q]);
    acc[0] += __uint_as_float(v.x);
    acc[1] += __uint_as_float(v.y);
    acc[2] += __uint_as_float(v.z);
    acc[3] += __uint_as_float(v.w);
}
template <int TPN>
__device__ __forceinline__ void gacc_f16(const uint4* __restrict__ gsrc, int idx, int q,
                                         float (&acc)[8]) {
    uint4 v = __ldcg(&gsrc[(size_t)idx * TPN + q]);
    float2 f0 = __half22float2(*(const __half2*)&v.x);
    float2 f1 = __half22float2(*(const __half2*)&v.y);
    float2 f2 = __half22float2(*(const __half2*)&v.z);
    float2 f3 = __half22float2(*(const __half2*)&v.w);
    acc[0] += f0.x; acc[1] += f0.y;
    acc[2] += f1.x; acc[3] += f1.y;
    acc[4] += f2.x; acc[5] += f2.y;
    acc[6] += f3.x; acc[7] += f3.y;
}
template <int TPN>
__device__ __forceinline__ void gacc_i8(const uint4* __restrict__ gsrc, int idx, int q,
                                        int (&acc)[16]) {
    uint4 v = __ldcg(&gsrc[(size_t)idx * TPN + q]);
    int w[4] = {(int)v.x, (int)v.y, (int)v.z, (int)v.w};
#pragma unroll
    for (int wi = 0; wi < 4; wi++) {
        acc[wi * 4 + 0] = __dp4a(w[wi], 0x00000001, acc[wi * 4 + 0]);
        acc[wi * 4 + 1] = __dp4a(w[wi], 0x00000100, acc[wi * 4 + 1]);
        acc[wi * 4 + 2] = __dp4a(w[wi], 0x00010000, acc[wi * 4 + 2]);
        acc[wi * 4 + 3] = __dp4a(w[wi], 0x01000000, acc[wi * 4 + 3]);
    }
}

// ---------------- fused SAGE layer (TG-thread node groups: TPN chunks x ES splits) ----
// TG = TPN*ES threads per node; NB = 256/TG nodes per block
template <int TPN, int ES, int GM, int FI, int FIS, int FO, bool RES, bool PRE, int GHM,
          int XFI, int XFO, bool MLPH>
__global__ void __launch_bounds__(256) k_sage(const uint4* __restrict__ gsrc,
                                              const float* __restrict__ xin,
                                              const float* __restrict__ res,
                                              float* __restrict__ xout,
                                              const float* __restrict__ wl,
                                              const float* __restrict__ bl,
                                              const float* __restrict__ wr,
                                              const float* __restrict__ xwl,
                                              void* __restrict__ ghout,
                                              const float* __restrict__ w1, const float* __restrict__ b1,
                                              const float* __restrict__ w2, const float* __restrict__ b2,
                                              const float* __restrict__ w3, const float* __restrict__ b3,
                                              float* __restrict__ mout) {
    constexpr int TG = TPN * ES;
    static_assert(TG == 4 || TG == 8, "node group of 4 or 8 lanes");
    constexpr int ELEM = (GM == GM_F32) ? 4 : (GM == GM_F16 ? 8 : 16);
    constexpr int HD = TPN * ELEM;
    constexpr int NB = 256 / TG;        // nodes per block
    constexpr bool SOUT = (XFO > 0) || MLPH;
    __shared__ __align__(16) float s_mean[NB * HD];
    __shared__ __align__(16) float s_wl[PRE ? 2 : FI * FO];
    __shared__ __align__(16) float s_wr[FI * FO];
    __shared__ float s_bl[FO];
    __shared__ __align__(16) float s_out[SOUT ? NB * FO : 1];
    __shared__ __align__(16) float s_xwl[XFO ? XFI * XFO : 1];
    __shared__ float m_w1[MLPH ? 256 : 1], m_b1[MLPH ? 32 : 1];
    __shared__ float m_w2[MLPH ? 512 : 1], m_b2[MLPH ? 16 : 1];
    __shared__ float m_w3[MLPH ? 32 : 1], m_b3[MLPH ? 2 : 1];
    int t = threadIdx.x;
    if constexpr (!PRE) { for (int i = t; i < FI * FO; i += 256) s_wl[i] = wl[i]; }
    for (int i = t; i < FI * FO; i += 256) s_wr[i] = wr[i];
    if constexpr (XFO > 0) { for (int i = t; i < XFI * XFO; i += 256) s_xwl[i] = xwl[i]; }
    if constexpr (MLPH) {
        if (t < 256) m_w1[t] = w1[t];
        for (int i = t; i < 512; i += 256) m_w2[i] = w2[i];
        if (t < 32) { m_b1[t] = b1[t]; m_w3[t] = w3[t]; }
        if (t < 16) m_b2[t] = b2[t];
        if (t < 2) m_b3[t] = b3[t];
    }
    if (t < FO) s_bl[t] = bl[t];

    int nbase = blockIdx.x * NB;

    // ---- phase 1: mean aggregation; TPN chunk-lanes x ES edge-split; depth-2 pipe ----
    {
        int nl = t / TG;
        int sub = t % TG;
        int q = sub % TPN;
        int es = sub / TPN;
        int n = nbase + nl;

        float accf[(GM == GM_I8) ? 1 : ELEM];
        int acci[(GM == GM_I8) ? 16 : 1];
#pragma unroll
        for (int k = 0; k < ((GM == GM_I8) ? 1 : ELEM); k++) accf[k] = 0.f;
#pragma unroll
        for (int k = 0; k < ((GM == GM_I8) ? 16 : 1); k++) acci[k] = 0;

        auto do_edge = [&](int idx) {
            if constexpr (GM == GM_F32) gacc_f32<TPN>(gsrc, idx, q, (float(&)[4])accf);
            else if constexpr (GM == GM_F16) gacc_f16<TPN>(gsrc, idx, q, (float(&)[8])accf);
            else gacc_i8<TPN>(gsrc, idx, q, acci);
        };

        if (n < N_NODES) {
            int start = g_row[n];                  // 4-aligned
            int dg = g_deg[n];
            const int* sp = g_srcs + start;
            int Q = dg >> 2;
            int nq = (Q > es) ? ((Q - es + ES - 1) / ES) : 0;
            if (nq > 0) {
                const int4* qp = (const int4*)sp + es;
                int4 c0 = __ldcg(qp);
                int4 c1;
                if (nq > 1) c1 = __ldcg(qp + ES);
                for (int i2 = 2; i2 < nq; i2++) {
                    int4 nx = __ldcg(qp + (size_t)i2 * ES);
                    do_edge(c0.x); do_edge(c0.y); do_edge(c0.z); do_edge(c0.w);
                    c0 = c1; c1 = nx;
                }
                do_edge(c0.x); do_edge(c0.y); do_edge(c0.z); do_edge(c0.w);
                if (nq > 1) { do_edge(c1.x); do_edge(c1.y); do_edge(c1.z); do_edge(c1.w); }
            }
            if (es == 0) {
                for (int e = Q * 4; e < dg; e++) do_edge(sp[e]);
            }
        }
        // reduce across edge-split lanes (stride TPN within the TG-lane group)
        if constexpr (GM == GM_I8) {
#pragma unroll
            for (int off = TPN; off < TG; off <<= 1)
#pragma unroll
                for (int k = 0; k < 16; k++)
                    acci[k] += __shfl_xor_sync(0xffffffffu, acci[k], off);
        } else {
#pragma unroll
            for (int off = TPN; off < TG; off <<= 1)
#pragma unroll
                for (int k = 0; k < ELEM; k++)
                    accf[k] += __shfl_xor_sync(0xffffffffu, accf[k], off);
        }
        if (n < N_NODES && es == 0) {
            float inv = g_invdeg[n];
            if constexpr (GM == GM_I8) {
                float sc = inv * (1.0f / 127.0f);
#pragma unroll
                for (int k = 0; k < 16; k++)
                    s_mean[nl * HD + q * 16 + k] = (float)acci[k] * sc;
            } else {
#pragma unroll
                for (int k = 0; k < ELEM; k++)
                    s_mean[nl * HD + q * ELEM + k] = accf[k] * inv;
            }
        }
    }
    __syncthreads();

    // ---- phase 2: out = tanh(mean@wl + bl + x@wr) [+res] ----
    constexpr int PAIRS = FO / 2;
    constexpr int NP2 = 256 / PAIRS;
    for (int p = 0; p < NB; p += NP2) {
        int nl2 = p + t / PAIRS;
        int fo2 = t % PAIRS;
        if (nl2 < NB) {
            int n = nbase + nl2;
            if (n < N_NODES) {
                float b0 = s_bl[2 * fo2], b1v = s_bl[2 * fo2 + 1];
                if constexpr (PRE) {
                    b0 += s_mean[nl2 * HD + 2 * fo2];
                    b1v += s_mean[nl2 * HD + 2 * fo2 + 1];
                }
                u64 v = pack2(b0, b1v);
                const float* xr = xin + (size_t)n * FIS;
#pragma unroll
                for (int i = 0; i < FI; i++) {
                    float xi = xr[i];
                    u64 xv = pack2(xi, xi);
                    v = fma2(xv, ((const u64*)s_wr)[i * PAIRS + fo2], v);
                    if constexpr (!PRE) {
                        float mi = s_mean[nl2 * HD + i];
                        u64 mv = pack2(mi, mi);
                        v = fma2(mv, ((const u64*)s_wl)[i * PAIRS + fo2], v);
                    }
                }
                float r0, r1; unpack2(v, r0, r1);
                r0 = tanh_fast(r0); r1 = tanh_fast(r1);
                if constexpr (RES) {
                    float2 rr = ((const float2*)res)[(size_t)n * PAIRS + fo2];
                    r0 += rr.x; r1 += rr.y;
                }
                if constexpr (!MLPH) {
                    ((float2*)xout)[(size_t)n * PAIRS + fo2] = make_float2(r0, r1);
                }
                if constexpr (GHM == GH_F16) {
                    ((__half2*)ghout)[(size_t)n * PAIRS + fo2] =
                        __float22half2_rn(make_float2(r0, r1));
                } else if constexpr (GHM == GH_I8) {
                    char2 cc;
                    cc.x = (char)__float2int_rn(r0 * 127.0f);
                    cc.y = (char)__float2int_rn(r1 * 127.0f);
                    ((char2*)ghout)[(size_t)n * PAIRS + fo2] = cc;
                }
                if constexpr (SOUT) {
                    s_out[nl2 * FO + 2 * fo2] = r0;
                    s_out[nl2 * FO + 2 * fo2 + 1] = r1;
                }
            }
        }
    }

    // ---- phase 3a: y = out @ xwl -> fp16 gather rows for next layer ----
    if constexpr (XFO > 0) {
        __syncthreads();
        for (int base = 0; base < NB * XFO; base += 256) {
            int idx2 = base + t;
            if (idx2 < NB * XFO) {
                int nl = idx2 / XFO, fo = idx2 % XFO;
                int n = nbase + nl;
                if (n < N_NODES) {
                    float v = 0.f;
#pragma unroll
                    for (int i = 0; i < XFI; i++)
                        v += s_out[nl * XFI + i] * s_xwl[i * XFO + fo];
                    ((__half*)ghout)[(size_t)n * XFO + fo] = __float2half_rn(v);
                }
            }
        }
    }

    // ---- phase 3b: fused MLP head + softmax (L7) ----
    if constexpr (MLPH) {
        __syncthreads();
        if (t < NB) {
            int n = nbase + t;
            if (n < N_NODES) {
                float in8[8];
#pragma unroll
                for (int i = 0; i < 8; i++) in8[i] = s_out[t * 8 + i];
                float a[32];
#pragma unroll
                for (int j = 0; j < 32; j++) {
                    float v = m_b1[j];
#pragma unroll
                    for (int i = 0; i < 8; i++) v += in8[i] * m_w1[i * 32 + j];
                    a[j] = tanh_fast(v);
                }
                float bb[16];
#pragma unroll
                for (int j = 0; j < 16; j++) {
                    float v = m_b2[j];
#pragma unroll
                    for (int i = 0; i < 32; i++) v += a[i] * m_w2[i * 16 + j];
                    bb[j] = tanh_fast(v);
                }
                float c0 = m_b3[0], c1 = m_b3[1];
#pragma unroll
                for (int i = 0; i < 16; i++) { c0 += bb[i] * m_w3[i * 2 + 0]; c1 += bb[i] * m_w3[i * 2 + 1]; }
                float m = fmaxf(c0, c1);
                float e0 = __expf(c0 - m), e1 = __expf(c1 - m);
                float inv = 1.f / (e0 + e1);
                ((float2*)mout)[n] = make_float2(e0 * inv, e1 * inv);
            }
        }
    }
}

// ---------------- launch ----------------
extern "C" void kernel_launch(void* const* d_in, const int* in_sizes, int n_in,
                              void* d_out, int out_size) {
    const float* x = (const float*)d_in[0];
    const int* ei = (const int*)d_in[1];
    const int* src = ei;
    const int* dst = ei + N_EDGES;

    const float* cw[7][3];
    for (int l = 0; l < 7; l++) {
        cw[l][0] = (const float*)d_in[2 + 3 * l + 0];
        cw[l][1] = (const float*)d_in[2 + 3 * l + 1];
        cw[l][2] = (const float*)d_in[2 + 3 * l + 2];
    }
    const float* lin1_w = (const float*)d_in[23];
    const float* lin1_b = (const float*)d_in[24];
    const float* lin2_w = (const float*)d_in[25];
    const float* lin2_b = (const float*)d_in[26];
    const float* lin3_w = (const float*)d_in[27];
    const float* lin3_b = (const float*)d_in[28];
    float* out = (float*)d_out;

    float *h0, *x1, *x2, *x3, *x4, *h5, *h6;
    uint4 *bufA, *bufB;
    cudaGetSymbolAddress((void**)&h0, g_h0);
    cudaGetSymbolAddress((void**)&x1, g_x1);
    cudaGetSymbolAddress((void**)&x2, g_x2);
    cudaGetSymbolAddress((void**)&x3, g_x3);
    cudaGetSymbolAddress((void**)&x4, g_x4);
    cudaGetSymbolAddress((void**)&h5, g_h5);
    cudaGetSymbolAddress((void**)&h6, g_h6);
    cudaGetSymbolAddress((void**)&bufA, g_bufA);
    cudaGetSymbolAddress((void**)&bufB, g_bufB);

    // setup + CSR build
    k_zero_init<<<NBLK_N, 256>>>();
    k_count_stats<<<NBLK_E4, 256>>>(dst, x);
    k_norm_scan1<<<NBLK_N, 256>>>(x);
    k_scan3<<<NBLK_N, 256>>>();
    k_scatter<<<NBLK_E4, 256>>>(src, dst);

    // L1: 3->8   gather h0 fp32 (TG=4: TPN=1,ES=4), NB=64 -> x1 + x1h fp16 (B)
    k_sage<1, 4, GM_F32, 3, 4, 8, false, false, GH_F16, 0, 0, false><<<1563, 256>>>(
        (const uint4*)h0, h0, nullptr, x1, cw[0][0], cw[0][1], cw[0][2], nullptr, bufB,
        nullptr, nullptr, nullptr, nullptr, nullptr, nullptr, nullptr);
    // L2: 8->16  gather x1h fp16 (B) (TG=4) -> x2 + x2 int8 (A)
    k_sage<1, 4, GM_F16, 8, 8, 16, false, false, GH_I8, 0, 0, false><<<1563, 256>>>(
        bufB, x1, nullptr, x2, cw[1][0], cw[1][1], cw[1][2], nullptr, bufA,
        nullptr, nullptr, nullptr, nullptr, nullptr, nullptr, nullptr);
    // L3: 16->32 gather x2 int8 (A, 1 chunk, TG=4) -> x3 + x3 int8 (B)
    k_sage<1, 4, GM_I8, 16, 16, 32, false, false, GH_I8, 0, 0, false><<<1563, 256>>>(
        bufA, x2, nullptr, x3, cw[2][0], cw[2][1], cw[2][2], nullptr, bufB,
        nullptr, nullptr, nullptr, nullptr, nullptr, nullptr, nullptr);
    // L4: 32->64 gather x3 int8 (B, 2 chunks, TG=8: TPN=2,ES=4), NB=32 -> x4 ; y5 -> A
    k_sage<2, 4, GM_I8, 32, 32, 64, false, false, GH_NONE, 64, 32, false><<<3125, 256>>>(
        bufB, x3, nullptr, x4, cw[3][0], cw[3][1], cw[3][2], cw[4][0], bufA,
        nullptr, nullptr, nullptr, nullptr, nullptr, nullptr, nullptr);
    // L5: (PRE) gather y5 fp16 (A, 4 chunks, TG=8: TPN=4,ES=2), NB=32, self x4, res x3 ; y6 -> B
    k_sage<4, 2, GM_F16, 64, 64, 32, true, true, GH_NONE, 32, 16, false><<<3125, 256>>>(
        bufA, x4, x3, h5, cw[4][0], cw[4][1], cw[4][2], cw[5][0], bufB,
        nullptr, nullptr, nullptr, nullptr, nullptr, nullptr, nullptr);
    // L6: (PRE) gather y6 fp16 (B, 2 chunks, TG=8: TPN=2,ES=4), NB=32, self h5, res x2 ; y7 -> A
    k_sage<2, 4, GM_F16, 32, 32, 16, true, true, GH_NONE, 16, 8, false><<<3125, 256>>>(
        bufB, h5, x2, h6, cw[5][0], cw[5][1], cw[5][2], cw[6][0], bufA,
        nullptr, nullptr, nullptr, nullptr, nullptr, nullptr, nullptr);
    // L7: (PRE) gather y7 fp16 (A, 1 chunk, TG=4), self h6, res x1 ; fused MLP head -> out
    k_sage<1, 4, GM_F16, 16, 16, 8, true, true, GH_NONE, 0, 0, true><<<1563, 256>>>(
        bufA, h6, x1, nullptr, cw[6][0], cw[6][1], cw[6][2], nullptr, nullptr,
        lin1_w, lin1_b, lin2_w, lin2_b, lin3_w, lin3_b, out);
}